// round 16
// baseline (speedup 1.0000x reference)
#include <cuda_runtime.h>
#include <math.h>

// ---------------------------------------------------------------------------
// MS-SSIM loss. 10 channels 1024x1024 fp32, 5 levels.
// Levels 0-3 contribute only CS, level 4 only SIM (reference's
// prod(pow1[:-1]*pow2[-1]) quirk) -> each level computes just one quantity.
// L0: standalone @ 4 CTAs/SM, interior-tile specialization.
// L1-L4 + combine: ONE persistent kernel (592 CTAs = full chip @ 4/SM) with
// software grid barriers. fp32 combine. 2 launches total.
// ---------------------------------------------------------------------------

#define NCH 10
#define TX 32
#define NBLK2 592   // 148 SMs x 4 resident CTAs (64 regs, 34KB smem)

__device__ constexpr float GW[11] = {
    0.00102842f, 0.00759877f, 0.03600077f, 0.10936076f, 0.21300535f,
    0.26601172f,
    0.21300535f, 0.10936076f, 0.03600077f, 0.00759877f, 0.00102842f};

__device__ float g_sim_acc[50];   // [level][channel] (only level 4 used)
__device__ float g_cs_acc[50];    // (only levels 0-3 used)
__device__ int g_bar_count;
__device__ int g_bar_gen;

#define SCR_TOTAL 3481600
__device__ __align__(16) float g_scr_p[SCR_TOTAL];
__device__ __align__(16) float g_scr_t[SCR_TOTAL];

#define OFF_L1 0
#define OFF_L2 2621440
#define OFF_L3 3276800
#define OFF_L4 3440640

// shared workspace sized for the largest tile (TY=54 -> 64 rows + 2 spare)
struct SmemWS {
    ulonglong2 hs[66][32];   // (s01, s2) packed pairs, bank-swizzled columns
    float rs[8];
};

__device__ __forceinline__ int swz(int col, int row) {
    return (col & 24) | (((col & 7) + ((col >> 3) & 3) + ((row & 1) << 2)) & 7);
}

// ---- f32x2 packed math helpers --------------------------------------------
typedef unsigned long long ull;

__device__ __forceinline__ ull pk2(float a, float b) {
    ull r; asm("mov.b64 %0, {%1, %2};" : "=l"(r) : "f"(a), "f"(b)); return r;
}
__device__ __forceinline__ void upk2(ull v, float& a, float& b) {
    asm("mov.b64 {%0, %1}, %2;" : "=f"(a), "=f"(b) : "l"(v));
}
#define FMA2(d, a, b, c) \
    asm("fma.rn.f32x2 %0, %1, %2, %3;" : "=l"(d) : "l"(a), "l"(b), "l"(c))
#define W2AT(i) W2[(i) < 6 ? (i) : 10 - (i)]

__device__ __forceinline__ void grid_barrier()
{
    __syncthreads();
    if (threadIdx.x == 0) {
        __threadfence();
        int gen = *((volatile int*)&g_bar_gen);
        if (atomicAdd(&g_bar_count, 1) == (int)gridDim.x - 1) {
            g_bar_count = 0;
            __threadfence();
            atomicAdd(&g_bar_gen, 1);
        } else {
            while (*((volatile int*)&g_bar_gen) == gen) { __nanosleep(128); }
        }
        __threadfence();
    }
    __syncthreads();
}

// ---------------------------------------------------------------------------
// One SSIM tile (+ fused pool). H, TY compile-time. Offset space (x - 0.5).
// EDGE=false: interior tile, no bounds checks. NEED_SIM: level-4 path.
// ---------------------------------------------------------------------------
template <int H, int TYV, bool DO_POOL, bool SUB, bool PERSIST, bool EDGE,
          bool NEED_SIM>
__device__ __forceinline__ void ssim_tile(
    SmemWS* ws,
    const float* __restrict__ P, const float* __restrict__ T,
    int level, int out_off, int ch, int bx, int by)
{
    constexpr int W = H;
    constexpr int OH = H - 10;
    constexpr int ROWS = TYV + 10;
    constexpr int OUT_PER = (TYV + 7) / 8;
    const int t = threadIdx.x;

    const float* Pc = P + (size_t)ch * (H * W);
    const float* Tc = T + (size_t)ch * (H * W);

    ull W2[6];
#pragma unroll
    for (int i = 0; i < 6; i++) W2[i] = pk2(GW[i], GW[i]);

    // ---------------- Stage A: horizontal pass + fused pool ----------------
    {
        const int r  = t >> 2;
        const int c0 = (t & 3) * 8;
        const int gy = by + r;
        const bool rowok = (r < ROWS) && (gy < H);
        const float* rowP = Pc + (size_t)gy * W + bx + c0;
        const float* rowT = Tc + (size_t)gy * W + bx + c0;

        ull s01[8], s2[8];
        float plP[4], plT[4];
#pragma unroll
        for (int j = 0; j < 8; j++) { s01[j] = 0ULL; s2[j] = 0ULL; }

        float4 pv4, tv4;
        if (EDGE) {
            pv4 = make_float4(0.f, 0.f, 0.f, 0.f);
            tv4 = make_float4(0.f, 0.f, 0.f, 0.f);
            if (rowok && (bx + c0) < W) {
                pv4 = *(const float4*)(rowP);
                tv4 = *(const float4*)(rowT);
            }
        } else {
            pv4 = *(const float4*)(rowP);
            tv4 = *(const float4*)(rowT);
        }

#pragma unroll
        for (int chk = 0; chk < 5; chk++) {
            float4 npv = make_float4(0.f, 0.f, 0.f, 0.f);
            float4 ntv = make_float4(0.f, 0.f, 0.f, 0.f);
            if (chk < 4) {
                if (EDGE) {
                    int ngx = bx + c0 + (chk + 1) * 4;
                    if (rowok && ngx < W) {
                        npv = *(const float4*)(rowP + (chk + 1) * 4);
                        ntv = *(const float4*)(rowT + (chk + 1) * 4);
                    }
                } else {
                    npv = *(const float4*)(rowP + (chk + 1) * 4);
                    ntv = *(const float4*)(rowT + (chk + 1) * 4);
                }
            }

            if (SUB) {
                pv4.x -= 0.5f; pv4.y -= 0.5f; pv4.z -= 0.5f; pv4.w -= 0.5f;
                tv4.x -= 0.5f; tv4.y -= 0.5f; tv4.z -= 0.5f; tv4.w -= 0.5f;
            }

            if (DO_POOL && chk < 2) {
                plP[chk * 2 + 0] = pv4.x + pv4.y;
                plP[chk * 2 + 1] = pv4.z + pv4.w;
                plT[chk * 2 + 0] = tv4.x + tv4.y;
                plT[chk * 2 + 1] = tv4.z + tv4.w;
            }

            const float pa[4] = {pv4.x, pv4.y, pv4.z, pv4.w};
            const float ta[4] = {tv4.x, tv4.y, tv4.z, tv4.w};
#pragma unroll
            for (int q = 0; q < 4; q++) {
                const int k = chk * 4 + q;
                if (k < 18) {
                    float pv = pa[q], tv = ta[q];
                    ull ptp = pk2(pv, tv);
                    float ssv = fmaf(pv, pv, tv * tv);   // p^2 + t^2
                    float ptv = pv * tv;
                    ull ssp = pk2(ssv, ptv);
#pragma unroll
                    for (int j = 0; j < 8; j++) {
                        const int i = k - j;
                        if (i >= 0 && i <= 10) {
                            FMA2(s01[j], W2AT(i), ptp, s01[j]);
                            FMA2(s2[j],  W2AT(i), ssp, s2[j]);
                        }
                    }
                }
            }

            if (DO_POOL && chk == 1) {
                float vp[4], vt[4];
#pragma unroll
                for (int q = 0; q < 4; q++) {
                    vp[q] = plP[q] + __shfl_down_sync(0xffffffffu, plP[q], 4);
                    vt[q] = plT[q] + __shfl_down_sync(0xffffffffu, plT[q], 4);
                }
                bool wr = ((r & 1) == 0) && (r + 1 < ROWS);
                if (EDGE) wr = wr && (gy + 1 < H);
                if (wr) {
                    constexpr int Ho = H >> 1;
                    size_t o = (size_t)ch * (Ho * Ho) + (size_t)(gy >> 1) * Ho
                               + ((bx + c0) >> 1);
                    *(float4*)(g_scr_p + out_off + o) =
                        make_float4(0.25f * vp[0], 0.25f * vp[1],
                                    0.25f * vp[2], 0.25f * vp[3]);
                    *(float4*)(g_scr_t + out_off + o) =
                        make_float4(0.25f * vt[0], 0.25f * vt[1],
                                    0.25f * vt[2], 0.25f * vt[3]);
                }
            }
            pv4 = npv; tv4 = ntv;
        }
        // swz(c0+j, r) = c0 | ((j + qoff) & 7), qoff = (c0>>3) + 4*(r&1)
        {
            ulonglong2* rowp = &ws->hs[r][c0];
            const int qoff = (c0 >> 3) + ((r & 1) << 2);
#pragma unroll
            for (int j = 0; j < 8; j++) {
                rowp[(j + qoff) & 7] = make_ulonglong2(s01[j], s2[j]);
            }
        }
    }
    __syncthreads();

    // ---------------- Stage B: vertical pass + SSIM ----------------
    const float C1v = 0.01f * 0.01f;
    const float C2v = 0.03f * 0.03f;
    float lacc = 0.f;     // cs-sum (levels 0-3) or sim-sum (level 4)
    {
        const int tx = t & 31;
        const int g  = t >> 5;
        const int r0 = g * OUT_PER;
        const int cnt = (TYV - r0) < OUT_PER ? (TYV - r0) : OUT_PER;
        const int ox = bx + tx;

        const int pr = r0 & 1;
        const ulonglong2* pe = &ws->hs[r0][swz(tx, pr)];
        const ulonglong2* po = &ws->hs[r0 + 1][swz(tx, pr ^ 1)];

        ull a01[OUT_PER], a2[OUT_PER];
#pragma unroll
        for (int j = 0; j < OUT_PER; j++) { a01[j] = 0ULL; a2[j] = 0ULL; }

#pragma unroll
        for (int k = 0; k < OUT_PER + 10; k++) {
            ulonglong2 h = (k & 1) ? po[((k - 1) >> 1) * 64]
                                   : pe[(k >> 1) * 64];
#pragma unroll
            for (int j = 0; j < OUT_PER; j++) {
                const int i = k - j;
                if (i >= 0 && i <= 10) {
                    FMA2(a01[j], W2AT(i), h.x, a01[j]);
                    FMA2(a2[j],  W2AT(i), h.y, a2[j]);
                }
            }
        }

#pragma unroll
        for (int j = 0; j < OUT_PER; j++) {
            int oy = by + r0 + j;
            bool valid = (j < cnt);
            if (EDGE) valid = valid && (oy < OH) && (ox < OH);
            if (valid) {
                float m1o, m2o, ssq, spt;
                upk2(a01[j], m1o, m2o);
                upk2(a2[j],  ssq, spt);
                float s12 = spt - m1o * m2o;
                float v2  = ssq - m1o * m1o - m2o * m2o + C2v;
                float v1 = 2.f * s12 + C2v;
                float cs = __fdividef(v1, v2);
                if (NEED_SIM) {
                    float m1 = m1o + 0.5f, m2 = m2o + 0.5f;
                    float m12 = m1 * m2;
                    float lum = __fdividef(2.f * m12 + C1v,
                                           fmaf(m1, m1, m2 * m2) + C1v);
                    lacc += cs * lum;
                } else {
                    lacc += cs;
                }
            }
        }
    }

#pragma unroll
    for (int o = 16; o > 0; o >>= 1)
        lacc += __shfl_down_sync(0xffffffff, lacc, o);
    if ((t & 31) == 0) ws->rs[t >> 5] = lacc;
    __syncthreads();
    if (t == 0) {
        float ss = 0.f;
#pragma unroll
        for (int i = 0; i < 8; i++) ss += ws->rs[i];
        float* dst = NEED_SIM ? g_sim_acc : g_cs_acc;
        atomicAdd(&dst[level * NCH + ch], ss);
    }
    if (PERSIST) __syncthreads();
}

// dispatch helper: interior tiles skip all bounds checks (TY=54 only)
template <int H, bool DO_POOL, bool SUB, bool PERSIST>
__device__ __forceinline__ void ssim_tile54(
    SmemWS* ws, const float* __restrict__ P, const float* __restrict__ T,
    int level, int out_off, int ch, int bx, int by)
{
    const bool interior = (bx + 48 <= H) && (by + 64 <= H);
    if (interior)
        ssim_tile<H, 54, DO_POOL, SUB, PERSIST, false, false>(
            ws, P, T, level, out_off, ch, bx, by);
    else
        ssim_tile<H, 54, DO_POOL, SUB, PERSIST, true, false>(
            ws, P, T, level, out_off, ch, bx, by);
}

// ---------------------------------------------------------------------------
// L0: standalone, one tile per CTA, 4 CTAs/SM target.
// ---------------------------------------------------------------------------
__global__ __launch_bounds__(256, 4)
void ssim_l0_kernel(const float* __restrict__ P, const float* __restrict__ T)
{
    __shared__ SmemWS ws;
    ssim_tile54<1024, true, true, false>(
        &ws, P, T, 0, OFF_L1, blockIdx.z, blockIdx.x * TX, blockIdx.y * 54);
}

// ---------------------------------------------------------------------------
// Persistent kernel: levels 1..4 with grid barriers, then fp32 combine.
// ---------------------------------------------------------------------------
template <int H, int TYV, bool DO_POOL, bool NEED_SIM>
__device__ __forceinline__ void run_level(SmemWS* ws, int level,
                                          int in_off, int out_off)
{
    constexpr int gx  = (H - 10 + TX - 1) / TX;
    constexpr int gyn = (H - 10 + TYV - 1) / TYV;
    constexpr int per_ch = gx * gyn;
    constexpr int tiles = per_ch * NCH;
    const float* Pl = (const float*)(g_scr_p + in_off);
    const float* Tl = (const float*)(g_scr_t + in_off);

#pragma unroll 1
    for (int w = blockIdx.x; w < tiles; w += gridDim.x) {
        int ch  = w / per_ch;
        int rem = w - ch * per_ch;
        int tyI = rem / gx;
        int txI = rem - tyI * gx;
        if (TYV == 54 && !NEED_SIM) {
            ssim_tile54<H, DO_POOL, false, true>(ws, Pl, Tl, level, out_off,
                                                 ch, txI * TX, tyI * TYV);
        } else {
            ssim_tile<H, TYV, DO_POOL, false, true, true, NEED_SIM>(
                ws, Pl, Tl, level, out_off, ch, txI * TX, tyI * TYV);
        }
    }
}

__global__ __launch_bounds__(256, 4)
void ssim_rest_kernel(float* __restrict__ out)
{
    __shared__ SmemWS ws;

    run_level<512, 54, true,  false>(&ws, 1, OFF_L1, OFF_L2);   // 1600 tiles
    grid_barrier();
    run_level<256, 54, true,  false>(&ws, 2, OFF_L2, OFF_L3);   // 400 tiles
    grid_barrier();
    run_level<128, 28, true,  false>(&ws, 3, OFF_L3, OFF_L4);   // 200 tiles
    grid_barrier();
    run_level<64,  14, false, true >(&ws, 4, OFF_L4, 0);        // 80 tiles
    grid_barrier();

    // fp32 combine: thread c (<10) handles category c.
    if (blockIdx.x == 0) {
        __shared__ float part[NCH];
        const int t = threadIdx.x;
        if (t < NCH) {
            const float w[5]    = {0.0448f, 0.2856f, 0.3001f, 0.2363f, 0.1333f};
            const float icnt[5] = {1.f / (1014.f * 1014.f), 1.f / (502.f * 502.f),
                                   1.f / (246.f * 246.f),  1.f / (118.f * 118.f),
                                   1.f / (54.f * 54.f)};
            float ms4 = g_sim_acc[4 * NCH + t] * icnt[4];
            float e = 4.0f * w[4] * log2f(ms4);
            for (int l = 0; l < 4; l++) {
                float mc = g_cs_acc[l * NCH + t] * icnt[l];
                e += w[l] * log2f(mc);
            }
            part[t] = exp2f(e);
        }
        __syncthreads();
        if (t == 0) {
            float total = 0.f;
            for (int c = 0; c < NCH; c++) total += part[c];
            out[0] = 1.0f - total;
        }
        if (t < 50) { g_sim_acc[t] = 0.f; g_cs_acc[t] = 0.f; }
    }
}

extern "C" void kernel_launch(void* const* d_in, const int* in_sizes, int n_in,
                              void* d_out, int out_size)
{
    const float* P = (const float*)d_in[0];
    const float* T = (const float*)d_in[1];
    float* out = (float*)d_out;

    dim3 grid0(32, 19, NCH);   // L0: 1024 -> OH 1014
    ssim_l0_kernel<<<grid0, 256>>>(P, T);
    ssim_rest_kernel<<<NBLK2, 256>>>(out);
}

// round 17
// speedup vs baseline: 1.0484x; 1.0484x over previous
#include <cuda_runtime.h>
#include <math.h>

// ---------------------------------------------------------------------------
// MS-SSIM loss. 10 channels 1024x1024 fp32, 5 levels.
// Levels 0-3 contribute only CS, level 4 only SIM (reference's
// prod(pow1[:-1]*pow2[-1]) quirk) -> each level computes one quantity.
// L0, L1: standalone @ 4 CTAs/SM (R16 showed persistent multi-wave levels
// stall at barriers; standalone wins for >1-wave levels).
// L2-L4: persistent kernel with 2 grid barriers; combine elected via atomic
// ticket (no final barrier).
// ---------------------------------------------------------------------------

#define NCH 10
#define TX 32
#define NBLK2 400

__device__ constexpr float GW[11] = {
    0.00102842f, 0.00759877f, 0.03600077f, 0.10936076f, 0.21300535f,
    0.26601172f,
    0.21300535f, 0.10936076f, 0.03600077f, 0.00759877f, 0.00102842f};

__device__ float g_sim_acc[50];   // [level][channel] (only level 4 used)
__device__ float g_cs_acc[50];    // (only levels 0-3 used)
__device__ int g_bar_count;
__device__ int g_bar_gen;
__device__ int g_ticket;

#define SCR_TOTAL 3481600
__device__ __align__(16) float g_scr_p[SCR_TOTAL];
__device__ __align__(16) float g_scr_t[SCR_TOTAL];

#define OFF_L1 0
#define OFF_L2 2621440
#define OFF_L3 3276800
#define OFF_L4 3440640

// shared workspace sized for the largest tile (TY=54 -> 64 rows + 2 spare)
struct SmemWS {
    ulonglong2 hs[66][32];   // (s01, s2) packed pairs, bank-swizzled columns
    float rs[8];
};

__device__ __forceinline__ int swz(int col, int row) {
    return (col & 24) | (((col & 7) + ((col >> 3) & 3) + ((row & 1) << 2)) & 7);
}

// ---- f32x2 packed math helpers --------------------------------------------
typedef unsigned long long ull;

__device__ __forceinline__ ull pk2(float a, float b) {
    ull r; asm("mov.b64 %0, {%1, %2};" : "=l"(r) : "f"(a), "f"(b)); return r;
}
__device__ __forceinline__ void upk2(ull v, float& a, float& b) {
    asm("mov.b64 {%0, %1}, %2;" : "=f"(a), "=f"(b) : "l"(v));
}
#define FMA2(d, a, b, c) \
    asm("fma.rn.f32x2 %0, %1, %2, %3;" : "=l"(d) : "l"(a), "l"(b), "l"(c))
#define W2AT(i) W2[(i) < 6 ? (i) : 10 - (i)]

__device__ __forceinline__ void grid_barrier()
{
    __syncthreads();
    if (threadIdx.x == 0) {
        __threadfence();
        int gen = *((volatile int*)&g_bar_gen);
        if (atomicAdd(&g_bar_count, 1) == (int)gridDim.x - 1) {
            g_bar_count = 0;
            __threadfence();
            atomicAdd(&g_bar_gen, 1);
        } else {
            while (*((volatile int*)&g_bar_gen) == gen) { __nanosleep(128); }
        }
        __threadfence();
    }
    __syncthreads();
}

// ---------------------------------------------------------------------------
// One SSIM tile (+ fused pool). H, TY compile-time. Offset space (x - 0.5).
// EDGE=false: interior tile, no bounds checks. NEED_SIM: level-4 path.
// ---------------------------------------------------------------------------
template <int H, int TYV, bool DO_POOL, bool SUB, bool PERSIST, bool EDGE,
          bool NEED_SIM>
__device__ __forceinline__ void ssim_tile(
    SmemWS* ws,
    const float* __restrict__ P, const float* __restrict__ T,
    int level, int out_off, int ch, int bx, int by)
{
    constexpr int W = H;
    constexpr int OH = H - 10;
    constexpr int ROWS = TYV + 10;
    constexpr int OUT_PER = (TYV + 7) / 8;
    const int t = threadIdx.x;

    const float* Pc = P + (size_t)ch * (H * W);
    const float* Tc = T + (size_t)ch * (H * W);

    ull W2[6];
#pragma unroll
    for (int i = 0; i < 6; i++) W2[i] = pk2(GW[i], GW[i]);

    // ---------------- Stage A: horizontal pass + fused pool ----------------
    {
        const int r  = t >> 2;
        const int c0 = (t & 3) * 8;
        const int gy = by + r;
        const bool rowok = (r < ROWS) && (gy < H);
        const float* rowP = Pc + (size_t)gy * W + bx + c0;
        const float* rowT = Tc + (size_t)gy * W + bx + c0;

        ull s01[8], s2[8];
        float plP[4], plT[4];
#pragma unroll
        for (int j = 0; j < 8; j++) { s01[j] = 0ULL; s2[j] = 0ULL; }

        float4 pv4, tv4;
        if (EDGE) {
            pv4 = make_float4(0.f, 0.f, 0.f, 0.f);
            tv4 = make_float4(0.f, 0.f, 0.f, 0.f);
            if (rowok && (bx + c0) < W) {
                pv4 = *(const float4*)(rowP);
                tv4 = *(const float4*)(rowT);
            }
        } else {
            pv4 = *(const float4*)(rowP);
            tv4 = *(const float4*)(rowT);
        }

#pragma unroll
        for (int chk = 0; chk < 5; chk++) {
            float4 npv = make_float4(0.f, 0.f, 0.f, 0.f);
            float4 ntv = make_float4(0.f, 0.f, 0.f, 0.f);
            if (chk < 4) {
                if (EDGE) {
                    int ngx = bx + c0 + (chk + 1) * 4;
                    if (rowok && ngx < W) {
                        npv = *(const float4*)(rowP + (chk + 1) * 4);
                        ntv = *(const float4*)(rowT + (chk + 1) * 4);
                    }
                } else {
                    npv = *(const float4*)(rowP + (chk + 1) * 4);
                    ntv = *(const float4*)(rowT + (chk + 1) * 4);
                }
            }

            if (SUB) {
                pv4.x -= 0.5f; pv4.y -= 0.5f; pv4.z -= 0.5f; pv4.w -= 0.5f;
                tv4.x -= 0.5f; tv4.y -= 0.5f; tv4.z -= 0.5f; tv4.w -= 0.5f;
            }

            if (DO_POOL && chk < 2) {
                plP[chk * 2 + 0] = pv4.x + pv4.y;
                plP[chk * 2 + 1] = pv4.z + pv4.w;
                plT[chk * 2 + 0] = tv4.x + tv4.y;
                plT[chk * 2 + 1] = tv4.z + tv4.w;
            }

            const float pa[4] = {pv4.x, pv4.y, pv4.z, pv4.w};
            const float ta[4] = {tv4.x, tv4.y, tv4.z, tv4.w};
#pragma unroll
            for (int q = 0; q < 4; q++) {
                const int k = chk * 4 + q;
                if (k < 18) {
                    float pv = pa[q], tv = ta[q];
                    ull ptp = pk2(pv, tv);
                    float ssv = fmaf(pv, pv, tv * tv);   // p^2 + t^2
                    float ptv = pv * tv;
                    ull ssp = pk2(ssv, ptv);
#pragma unroll
                    for (int j = 0; j < 8; j++) {
                        const int i = k - j;
                        if (i >= 0 && i <= 10) {
                            FMA2(s01[j], W2AT(i), ptp, s01[j]);
                            FMA2(s2[j],  W2AT(i), ssp, s2[j]);
                        }
                    }
                }
            }

            if (DO_POOL && chk == 1) {
                float vp[4], vt[4];
#pragma unroll
                for (int q = 0; q < 4; q++) {
                    vp[q] = plP[q] + __shfl_down_sync(0xffffffffu, plP[q], 4);
                    vt[q] = plT[q] + __shfl_down_sync(0xffffffffu, plT[q], 4);
                }
                bool wr = ((r & 1) == 0) && (r + 1 < ROWS);
                if (EDGE) wr = wr && (gy + 1 < H);
                if (wr) {
                    constexpr int Ho = H >> 1;
                    size_t o = (size_t)ch * (Ho * Ho) + (size_t)(gy >> 1) * Ho
                               + ((bx + c0) >> 1);
                    *(float4*)(g_scr_p + out_off + o) =
                        make_float4(0.25f * vp[0], 0.25f * vp[1],
                                    0.25f * vp[2], 0.25f * vp[3]);
                    *(float4*)(g_scr_t + out_off + o) =
                        make_float4(0.25f * vt[0], 0.25f * vt[1],
                                    0.25f * vt[2], 0.25f * vt[3]);
                }
            }
            pv4 = npv; tv4 = ntv;
        }
        // swz(c0+j, r) = c0 | ((j + qoff) & 7), qoff = (c0>>3) + 4*(r&1)
        {
            ulonglong2* rowp = &ws->hs[r][c0];
            const int qoff = (c0 >> 3) + ((r & 1) << 2);
#pragma unroll
            for (int j = 0; j < 8; j++) {
                rowp[(j + qoff) & 7] = make_ulonglong2(s01[j], s2[j]);
            }
        }
    }
    __syncthreads();

    // ---------------- Stage B: vertical pass + SSIM ----------------
    const float C1v = 0.01f * 0.01f;
    const float C2v = 0.03f * 0.03f;
    float lacc = 0.f;     // cs-sum (levels 0-3) or sim-sum (level 4)
    {
        const int tx = t & 31;
        const int g  = t >> 5;
        const int r0 = g * OUT_PER;
        const int cnt = (TYV - r0) < OUT_PER ? (TYV - r0) : OUT_PER;
        const int ox = bx + tx;

        const int pr = r0 & 1;
        const ulonglong2* pe = &ws->hs[r0][swz(tx, pr)];
        const ulonglong2* po = &ws->hs[r0 + 1][swz(tx, pr ^ 1)];

        ull a01[OUT_PER], a2[OUT_PER];
#pragma unroll
        for (int j = 0; j < OUT_PER; j++) { a01[j] = 0ULL; a2[j] = 0ULL; }

#pragma unroll
        for (int k = 0; k < OUT_PER + 10; k++) {
            ulonglong2 h = (k & 1) ? po[((k - 1) >> 1) * 64]
                                   : pe[(k >> 1) * 64];
#pragma unroll
            for (int j = 0; j < OUT_PER; j++) {
                const int i = k - j;
                if (i >= 0 && i <= 10) {
                    FMA2(a01[j], W2AT(i), h.x, a01[j]);
                    FMA2(a2[j],  W2AT(i), h.y, a2[j]);
                }
            }
        }

#pragma unroll
        for (int j = 0; j < OUT_PER; j++) {
            int oy = by + r0 + j;
            bool valid = (j < cnt);
            if (EDGE) valid = valid && (oy < OH) && (ox < OH);
            if (valid) {
                float m1o, m2o, ssq, spt;
                upk2(a01[j], m1o, m2o);
                upk2(a2[j],  ssq, spt);
                float s12 = spt - m1o * m2o;
                float v2  = ssq - m1o * m1o - m2o * m2o + C2v;
                float v1 = 2.f * s12 + C2v;
                float cs = __fdividef(v1, v2);
                if (NEED_SIM) {
                    float m1 = m1o + 0.5f, m2 = m2o + 0.5f;
                    float m12 = m1 * m2;
                    float lum = __fdividef(2.f * m12 + C1v,
                                           fmaf(m1, m1, m2 * m2) + C1v);
                    lacc += cs * lum;
                } else {
                    lacc += cs;
                }
            }
        }
    }

#pragma unroll
    for (int o = 16; o > 0; o >>= 1)
        lacc += __shfl_down_sync(0xffffffff, lacc, o);
    if ((t & 31) == 0) ws->rs[t >> 5] = lacc;
    __syncthreads();
    if (t == 0) {
        float ss = 0.f;
#pragma unroll
        for (int i = 0; i < 8; i++) ss += ws->rs[i];
        float* dst = NEED_SIM ? g_sim_acc : g_cs_acc;
        atomicAdd(&dst[level * NCH + ch], ss);
    }
    if (PERSIST) __syncthreads();
}

// dispatch helper: interior tiles skip all bounds checks (TY=54 only)
template <int H, bool DO_POOL, bool SUB, bool PERSIST>
__device__ __forceinline__ void ssim_tile54(
    SmemWS* ws, const float* __restrict__ P, const float* __restrict__ T,
    int level, int out_off, int ch, int bx, int by)
{
    const bool interior = (bx + 48 <= H) && (by + 64 <= H);
    if (interior)
        ssim_tile<H, 54, DO_POOL, SUB, PERSIST, false, false>(
            ws, P, T, level, out_off, ch, bx, by);
    else
        ssim_tile<H, 54, DO_POOL, SUB, PERSIST, true, false>(
            ws, P, T, level, out_off, ch, bx, by);
}

// ---------------------------------------------------------------------------
// L0 / L1: standalone, one tile per CTA, 4 CTAs/SM target.
// ---------------------------------------------------------------------------
__global__ __launch_bounds__(256, 4)
void ssim_l0_kernel(const float* __restrict__ P, const float* __restrict__ T)
{
    __shared__ SmemWS ws;
    ssim_tile54<1024, true, true, false>(
        &ws, P, T, 0, OFF_L1, blockIdx.z, blockIdx.x * TX, blockIdx.y * 54);
}

__global__ __launch_bounds__(256, 4)
void ssim_l1_kernel()
{
    __shared__ SmemWS ws;
    ssim_tile54<512, true, false, false>(
        &ws, g_scr_p + OFF_L1, g_scr_t + OFF_L1, 1, OFF_L2,
        blockIdx.z, blockIdx.x * TX, blockIdx.y * 54);
}

// ---------------------------------------------------------------------------
// Persistent kernel: levels 2..4 with 2 grid barriers; combine CTA elected
// via atomic ticket (no final barrier - other CTAs exit immediately).
// ---------------------------------------------------------------------------
template <int H, int TYV, bool DO_POOL, bool NEED_SIM>
__device__ __forceinline__ void run_level(SmemWS* ws, int level,
                                          int in_off, int out_off)
{
    constexpr int gx  = (H - 10 + TX - 1) / TX;
    constexpr int gyn = (H - 10 + TYV - 1) / TYV;
    constexpr int per_ch = gx * gyn;
    constexpr int tiles = per_ch * NCH;
    const float* Pl = (const float*)(g_scr_p + in_off);
    const float* Tl = (const float*)(g_scr_t + in_off);

#pragma unroll 1
    for (int w = blockIdx.x; w < tiles; w += gridDim.x) {
        int ch  = w / per_ch;
        int rem = w - ch * per_ch;
        int tyI = rem / gx;
        int txI = rem - tyI * gx;
        if (TYV == 54 && !NEED_SIM) {
            ssim_tile54<H, DO_POOL, false, true>(ws, Pl, Tl, level, out_off,
                                                 ch, txI * TX, tyI * TYV);
        } else {
            ssim_tile<H, TYV, DO_POOL, false, true, true, NEED_SIM>(
                ws, Pl, Tl, level, out_off, ch, txI * TX, tyI * TYV);
        }
    }
}

__global__ __launch_bounds__(256, 3)
void ssim_rest_kernel(float* __restrict__ out)
{
    __shared__ SmemWS ws;
    __shared__ int elected;

    run_level<256, 54, true,  false>(&ws, 2, OFF_L2, OFF_L3);   // 400 tiles
    grid_barrier();
    run_level<128, 28, true,  false>(&ws, 3, OFF_L3, OFF_L4);   // 200 tiles
    grid_barrier();
    run_level<64,  14, false, true >(&ws, 4, OFF_L4, 0);        // 80 tiles

    // ticket election: the CTA drawing the last ticket is provably last ->
    // all accumulations are L2-visible (fenced before the ticket atomic).
    __syncthreads();
    if (threadIdx.x == 0) {
        __threadfence();
        int tk = atomicAdd(&g_ticket, 1);
        elected = (tk == (int)gridDim.x - 1) ? 1 : 0;
    }
    __syncthreads();
    if (!elected) return;

    // fp32 combine (elected CTA): thread c (<10) handles category c.
    {
        __shared__ float part[NCH];
        const int t = threadIdx.x;
        __threadfence();
        if (t < NCH) {
            const float w[5]    = {0.0448f, 0.2856f, 0.3001f, 0.2363f, 0.1333f};
            const float icnt[5] = {1.f / (1014.f * 1014.f), 1.f / (502.f * 502.f),
                                   1.f / (246.f * 246.f),  1.f / (118.f * 118.f),
                                   1.f / (54.f * 54.f)};
            volatile float* vsim = g_sim_acc;
            volatile float* vcs  = g_cs_acc;
            float ms4 = vsim[4 * NCH + t] * icnt[4];
            float e = 4.0f * w[4] * log2f(ms4);
            for (int l = 0; l < 4; l++) {
                float mc = vcs[l * NCH + t] * icnt[l];
                e += w[l] * log2f(mc);
            }
            part[t] = exp2f(e);
        }
        __syncthreads();
        if (t == 0) {
            float total = 0.f;
            for (int c = 0; c < NCH; c++) total += part[c];
            out[0] = 1.0f - total;
            g_ticket = 0;   // reset for next replay
        }
        if (t < 50) { g_sim_acc[t] = 0.f; g_cs_acc[t] = 0.f; }
    }
}

extern "C" void kernel_launch(void* const* d_in, const int* in_sizes, int n_in,
                              void* d_out, int out_size)
{
    const float* P = (const float*)d_in[0];
    const float* T = (const float*)d_in[1];
    float* out = (float*)d_out;

    dim3 grid0(32, 19, NCH);   // L0: 1024 -> OH 1014
    ssim_l0_kernel<<<grid0, 256>>>(P, T);
    dim3 grid1(16, 10, NCH);   // L1: 512 -> OH 502
    ssim_l1_kernel<<<grid1, 256>>>();
    ssim_rest_kernel<<<NBLK2, 256>>>(out);
}